// round 1
// baseline (speedup 1.0000x reference)
#include <cuda_runtime.h>
#include <math.h>

#define NB 256
#define HH 26
#define WW 26
#define LL 624
#define DDc 128
#define CHc 256
#define HWc (HH*WW)

// Scratch (device globals — no allocation allowed in kernel_launch)
__device__ float g_Y [(size_t)NB*HWc*DDc];   // grid state, updated per layer
__device__ float g_Yn[(size_t)NB*HWc*DDc];   // layernorm output
__device__ int   g_inv[HWc];                 // grid cell -> token index or -1

typedef unsigned long long u64;

__device__ __forceinline__ u64 pk2(float lo, float hi){
  u64 r; asm("mov.b64 %0, {%1, %2};" : "=l"(r) : "f"(lo), "f"(hi)); return r;
}
__device__ __forceinline__ void fma2(u64 &d, u64 a, u64 b){
  asm("fma.rn.f32x2 %0, %1, %2, %0;" : "+l"(d) : "l"(a), "l"(b));
}
__device__ __forceinline__ float2 upk2(u64 v){
  float2 f; asm("mov.b64 {%0, %1}, %2;" : "=f"(f.x), "=f"(f.y) : "l"(v)); return f;
}

// Build inverse scatter map (single block)
__global__ void k_inv(const int* __restrict__ coords){
  int t = threadIdx.x;
  if (t < HWc) g_inv[t] = -1;
  __syncthreads();
  if (t < LL){
    int r = coords[2*t], c = coords[2*t+1];
    g_inv[r*WW + c] = t;
  }
}

// Y[b,h,w,:] = X[b, inv(h,w), :] or P
__global__ void k_fill(const float* __restrict__ X, const float* __restrict__ P){
  unsigned idx = blockIdx.x*256u + threadIdx.x;
  if (idx >= (unsigned)NB*HWc*DDc) return;
  int c = idx & (DDc-1);
  int s = (idx >> 7) % HWc;
  int b = idx / (DDc*HWc);
  int li = g_inv[s];
  g_Y[idx] = (li >= 0) ? X[((size_t)b*LL + li)*DDc + c] : P[c];
}

// Row-wise LayerNorm over channel dim (128), one block per (b,h,w)
__global__ void k_ln(const float* __restrict__ scale, const float* __restrict__ bias){
  int row = blockIdx.x;
  int c = threadIdx.x;
  float x = g_Y[(size_t)row*DDc + c];
  float s = x, s2 = x*x;
  #pragma unroll
  for (int o=16;o;o>>=1){
    s  += __shfl_xor_sync(0xffffffffu, s , o);
    s2 += __shfl_xor_sync(0xffffffffu, s2, o);
  }
  __shared__ float sh[8];
  int wid=c>>5, lane=c&31;
  if(!lane){ sh[wid]=s; sh[4+wid]=s2; }
  __syncthreads();
  float ts  = sh[0]+sh[1]+sh[2]+sh[3];
  float ts2 = sh[4]+sh[5]+sh[6]+sh[7];
  float m = ts*(1.0f/DDc);
  float v = ts2*(1.0f/DDc) - m*m;
  float r = rsqrtf(v + 1e-5f);
  g_Yn[(size_t)row*DDc + c] = (x-m)*r*scale[c] + bias[c];
}

// Fused: 3x3 conv (128->256) + bias + exact gelu + 1x1 (256->128) + bias + residual.
// One block per (b, output row h). 256 threads = 256 conv output channels.
__global__ __launch_bounds__(256) void k_conv(
    const float* __restrict__ w3l, const float* __restrict__ b3l,
    const float* __restrict__ w1l, const float* __restrict__ b1l){
  // Transposed, zero-padded neighborhood: sT[dy][ci][w+1], rows of 28 floats.
  __shared__ float sT[3*DDc*28];   // 43008 B (< 48KB static limit)
  int bh = blockIdx.x;
  int b = bh / HH, h = bh % HH;
  int t = threadIdx.x;

  for (int i=t;i<3*DDc*28;i+=256) sT[i]=0.f;
  __syncthreads();
  const float* Ynb = g_Yn + (size_t)b*HWc*DDc;
  for (int dy=0;dy<3;dy++){
    int hh=h-1+dy;
    if (hh<0||hh>=HH) continue;
    const float* rowp = Ynb + (size_t)hh*WW*DDc;
    for (int i=t;i<WW*DDc;i+=256){
      int w=i>>7, ci=i&127;
      sT[(dy*DDc+ci)*28 + 1 + w] = rowp[i];    // coalesced read, 4-way-conflict write (ok)
    }
  }
  __syncthreads();

  // acc[j] = packed (out[w=2j], out[w=2j+1]) for this co=t
  u64 acc[13];
  {
    float bv=b3l[t];
    u64 bp=pk2(bv,bv);
    #pragma unroll
    for(int j=0;j<13;j++) acc[j]=bp;
  }
  for (int dy=0;dy<3;dy++){
    const float* wb  = w3l + dy*3*DDc*CHc + t;   // +[dx][ci]*CHc
    const float* sdy = sT + dy*DDc*28;
    #pragma unroll 2
    for (int ci=0;ci<DDc;ci++){
      // 28-wide window: 7 broadcast LDS.128 feed 39 FFMA2 (78 FMAs)
      float win[28];
      const float4* wp = (const float4*)(sdy + ci*28);
      #pragma unroll
      for(int q=0;q<7;q++){
        float4 v4 = wp[q];
        win[4*q]=v4.x; win[4*q+1]=v4.y; win[4*q+2]=v4.z; win[4*q+3]=v4.w;
      }
      float wv0 = wb[(0*DDc+ci)*CHc];
      float wv1 = wb[(1*DDc+ci)*CHc];
      float wv2 = wb[(2*DDc+ci)*CHc];
      u64 q0=pk2(wv0,wv0), q1=pk2(wv1,wv1), q2=pk2(wv2,wv2);
      #pragma unroll
      for(int j=0;j<13;j++){
        fma2(acc[j], pk2(win[2*j  ],win[2*j+1]), q0);  // dx=0
        fma2(acc[j], pk2(win[2*j+1],win[2*j+2]), q1);  // dx=1
        fma2(acc[j], pk2(win[2*j+2],win[2*j+3]), q2);  // dx=2 (CSEs with dx=0 of j+1)
      }
    }
  }
  __syncthreads();            // all threads done reading sT
  float* g = sT;              // reuse smem as gelu output [26][256] (6656 <= 10752 floats)
  #pragma unroll
  for(int j=0;j<13;j++){
    float2 v=upk2(acc[j]);
    g[(2*j  )*CHc+t]=0.5f*v.x*(1.f+erff(v.x*0.70710678118654752f));
    g[(2*j+1)*CHc+t]=0.5f*v.y*(1.f+erff(v.y*0.70710678118654752f));
  }
  __syncthreads();

  // 1x1: out[w][d] = b1[d] + sum_co g[w][co] * w1[co][d]; residual into g_Y
  float* Yrow = g_Y + ((size_t)b*HWc + (size_t)h*WW)*DDc;
  int d  = t & (DDc-1);
  int w0 = t >> 7;
  const float* w1d = w1l + d;
  for (int w=w0; w<WW; w+=2){
    u64 a2 = 0;   // packed (0.f, 0.f)
    const float4* g4 = (const float4*)(g + w*CHc);
    #pragma unroll 8
    for(int co=0;co<CHc;co+=4){
      float4 gv = g4[co>>2];                                // broadcast LDS.128
      fma2(a2, pk2(gv.x,gv.y), pk2(w1d[(co  )*DDc], w1d[(co+1)*DDc]));
      fma2(a2, pk2(gv.z,gv.w), pk2(w1d[(co+2)*DDc], w1d[(co+3)*DDc]));
    }
    float2 af=upk2(a2);
    Yrow[w*DDc + d] += b1l[d] + af.x + af.y;
  }
}

__global__ void k_gather(const int* __restrict__ coords, float* __restrict__ out){
  unsigned idx = blockIdx.x*256u + threadIdx.x;
  if (idx >= (unsigned)NB*LL*DDc) return;
  int c = idx & (DDc-1);
  int l = (idx >> 7) % LL;
  int b = idx / (DDc*LL);
  int r=coords[2*l], cc=coords[2*l+1];
  out[idx] = g_Y[((size_t)b*HWc + r*WW + cc)*DDc + c];
}

extern "C" void kernel_launch(void* const* d_in, const int* in_sizes, int n_in,
                              void* d_out, int out_size){
  const float* X        = (const float*)d_in[0];
  const int*   coords   = (const int*)  d_in[1];
  const float* P        = (const float*)d_in[2];
  const float* ln_scale = (const float*)d_in[3];
  const float* ln_bias  = (const float*)d_in[4];
  const float* w3       = (const float*)d_in[5];
  const float* b3       = (const float*)d_in[6];
  const float* w1       = (const float*)d_in[7];
  const float* b1       = (const float*)d_in[8];
  float* out = (float*)d_out;

  k_inv<<<1, 1024>>>(coords);

  unsigned tot = (unsigned)NB*HWc*DDc;           // 22,151,168
  k_fill<<<(tot+255u)/256u, 256>>>(X, P);

  for (int l=0;l<4;l++){
    k_ln<<<NB*HWc, 128>>>(ln_scale + l*DDc, ln_bias + l*DDc);
    k_conv<<<NB*HH, 256>>>(w3 + (size_t)l*9*DDc*CHc, b3 + l*CHc,
                           w1 + (size_t)l*CHc*DDc,   b1 + l*DDc);
  }

  unsigned tz = (unsigned)NB*LL*DDc;             // 20,447,232
  k_gather<<<(tz+255u)/256u, 256>>>(coords, out);
}

// round 3
// speedup vs baseline: 6.8920x; 6.8920x over previous
#include <cuda_runtime.h>
#include <cuda_bf16.h>
#include <stdint.h>
#include <math.h>

#define NBt 256
#define POS 676          // 26*26
#define LLt 624
#define DDc 128
#define CHc 256
#define HP  28           // padded grid 28x28
#define NTILE 1352       // NBt*POS/128 (exact)

// ---- device-global scratch ----
__device__ float          g_Y  [(size_t)NBt*POS*DDc];      // residual stream, fp32
__device__ __nv_bfloat16  g_Ynp[(size_t)NBt*HP*HP*DDc];    // LN out, bf16, zero-padded
__device__ __nv_bfloat16  g_w3T[(size_t)4*9*CHc*DDc];      // [l][tap][co][ci]
__device__ __nv_bfloat16  g_w1T[(size_t)4*DDc*CHc];        // [l][d][co]
__device__ int            g_inv[POS];

// ---------------- PTX helpers (baseline PTX only, no sm_103a features) ----------------
__device__ __forceinline__ uint32_t s2u(const void* p){
  uint32_t a;
  asm("{ .reg .u64 t; cvta.to.shared.u64 t, %1; cvt.u32.u64 %0, t; }" : "=r"(a) : "l"(p));
  return a;
}
#define CP16(dst, src) asm volatile("cp.async.cg.shared.global [%0], [%1], 16;" :: "r"(dst), "l"(src) : "memory")
#define CP_COMMIT()    asm volatile("cp.async.commit_group;" ::: "memory")
#define CP_WAIT(n)     asm volatile("cp.async.wait_group %0;" :: "n"(n) : "memory")

__device__ __forceinline__ void ldsm4(uint32_t addr, uint32_t &r0, uint32_t &r1, uint32_t &r2, uint32_t &r3){
  asm volatile("ldmatrix.sync.aligned.m8n8.x4.shared.b16 {%0,%1,%2,%3}, [%4];"
    : "=r"(r0),"=r"(r1),"=r"(r2),"=r"(r3) : "r"(addr));
}
__device__ __forceinline__ void mma16816(float* c, uint32_t a0,uint32_t a1,uint32_t a2,uint32_t a3,
                                         uint32_t b0,uint32_t b1){
  asm volatile("mma.sync.aligned.m16n8k16.row.col.f32.bf16.bf16.f32 "
    "{%0,%1,%2,%3}, {%4,%5,%6,%7}, {%8,%9}, {%0,%1,%2,%3};"
    : "+f"(c[0]),"+f"(c[1]),"+f"(c[2]),"+f"(c[3])
    : "r"(a0),"r"(a1),"r"(a2),"r"(a3),"r"(b0),"r"(b1));
}

// ---------------- small kernels ----------------
__global__ void k_inv(const int* __restrict__ coords){
  int t = threadIdx.x;
  if (t < POS) g_inv[t] = -1;
  __syncthreads();
  if (t < LLt){
    int r = coords[2*t], c = coords[2*t+1];
    g_inv[r*26 + c] = t;
  }
}

__global__ void k_fill(const float* __restrict__ X, const float* __restrict__ P){
  unsigned idx = blockIdx.x*256u + threadIdx.x;
  int c = idx & (DDc-1);
  int s = (idx >> 7) % POS;
  int b = (idx >> 7) / POS;
  int li = g_inv[s];
  g_Y[idx] = (li >= 0) ? X[((size_t)b*LLt + li)*DDc + c] : P[c];
}

__global__ void k_zero(){
  size_t i = (size_t)blockIdx.x*256 + threadIdx.x;
  ((uint4*)g_Ynp)[i] = make_uint4(0,0,0,0);
}

__global__ void k_prep3(const float* __restrict__ w3){
  int idx = blockIdx.x*256 + threadIdx.x;     // < 4*9*256*128
  int ci = idx & 127;
  int co = (idx>>7) & 255;
  int lt = idx>>15;                           // l*9 + tap
  g_w3T[idx] = __float2bfloat16(w3[((size_t)lt*128 + ci)*256 + co]);
}

__global__ void k_prep1(const float* __restrict__ w1){
  int idx = blockIdx.x*256 + threadIdx.x;     // < 4*128*256
  int co = idx & 255;
  int d  = (idx>>8) & 127;
  int l  = idx>>15;
  g_w1T[idx] = __float2bfloat16(w1[((size_t)l*256 + co)*128 + d]);
}

// warp-per-cell LayerNorm, fp32 in -> bf16 padded grid out
__global__ void k_ln(const float* __restrict__ scale, const float* __restrict__ bias){
  int cell = blockIdx.x*8 + (threadIdx.x>>5);
  int lane = threadIdx.x & 31;
  const float* x = g_Y + (size_t)cell*DDc;
  float v0=x[lane], v1=x[lane+32], v2=x[lane+64], v3=x[lane+96];
  float s  = v0+v1+v2+v3;
  float s2 = v0*v0+v1*v1+v2*v2+v3*v3;
  #pragma unroll
  for (int o=16;o;o>>=1){ s += __shfl_xor_sync(~0u,s,o); s2 += __shfl_xor_sync(~0u,s2,o); }
  float mn = s*(1.f/128.f);
  float var = s2*(1.f/128.f) - mn*mn;
  float rs = rsqrtf(var + 1e-5f);
  int b = cell/POS, sp = cell - b*POS;
  int h = sp/26, w = sp - h*26;
  __nv_bfloat16* o = g_Ynp + (((size_t)b*HP + h+1)*HP + (w+1))*DDc;
  o[lane]    = __float2bfloat16((v0-mn)*rs*scale[lane]    + bias[lane]);
  o[lane+32] = __float2bfloat16((v1-mn)*rs*scale[lane+32] + bias[lane+32]);
  o[lane+64] = __float2bfloat16((v2-mn)*rs*scale[lane+64] + bias[lane+64]);
  o[lane+96] = __float2bfloat16((v3-mn)*rs*scale[lane+96] + bias[lane+96]);
}

__global__ void k_gather(const int* __restrict__ coords, float* __restrict__ out){
  unsigned idx = blockIdx.x*256u + threadIdx.x;
  int c = idx & (DDc-1);
  int l = (idx >> 7) % LLt;
  int b = (idx >> 7) / LLt;
  int r = coords[2*l], cc = coords[2*l+1];
  out[idx] = g_Y[((size_t)b*POS + r*26 + cc)*DDc + c];
}

// ---------------- fused conv block via mma.sync (HMMA, baseline PTX) ----------------
// One block = 128 flattened positions. Conv: 9 taps x K=128 accumulate 128x256 in
// registers (8 warps, 64x64 warp tiles). Epilogue: bias+gelu -> bf16 G in SMEM;
// 1x1 GEMM (K=256 -> N=128); bias + residual RMW into g_Y.
__global__ void __launch_bounds__(256,1) k_conv(
    int layer, const float* __restrict__ b3, const float* __restrict__ b1)
{
  extern __shared__ unsigned char smraw[];
  uint32_t sb0 = s2u(smraw);
  uint32_t pad = (0u - sb0) & 1023u;
  unsigned char* smem = smraw + pad;
  const uint32_t sbase = sb0 + pad;

  const int tid = threadIdx.x, lane = tid&31, wid = tid>>5;
  const int wm = wid & 1;          // 2-way M split (64 rows each)
  const int wn = wid >> 1;         // 4-way N split (64 cols each)
  const int lr = lane & 15;        // ldmatrix source-row lane component
  const int hi = lane >> 4;        // chunk-select lane component
  const int sw = lane & 7;         // swizzle key (== lr&7)

  enum { OFF_TAB=0, OFF_A0=1024, OFF_A1=1024+32768,
         OFF_B0=1024+65536, OFF_B1=1024+65536+65536 };   // end = 197632

  int* baseT = (int*)(smem + OFF_TAB);
  if (tid < 128){
    int p = blockIdx.x*128 + tid;
    int b = p/POS, sp = p - b*POS;
    int r = sp/26, c = sp - r*26;
    baseT[tid] = ((b*HP + r)*HP + c)*DDc;     // element offset of 3x3 window top-left
  }
  __syncthreads();

  const __nv_bfloat16* w3T = g_w3T + (size_t)layer*9*CHc*DDc;
  const __nv_bfloat16* w1T = g_w1T + (size_t)layer*DDc*CHc;

  // ---- tile loaders (cp.async, 16B chunks, XOR-swizzled for ldmatrix) ----
  #define LOAD_TAP(T_, AOFF, BOFF) do{                                          \
    const int tapoff = (((T_)/3)*HP + ((T_)%3))*DDc;                             \
    _Pragma("unroll")                                                            \
    for (int it=0; it<8; it++){                                                  \
      int seg = tid + it*256; int m = seg>>4, c = seg&15;                        \
      const __nv_bfloat16* src = g_Ynp + (size_t)(baseT[m] + tapoff) + c*8;      \
      uint32_t dst = sbase + (AOFF) + m*256 + ((c ^ (m&7))<<4);                  \
      CP16(dst, src);                                                            \
    }                                                                            \
    const __nv_bfloat16* wsrc = w3T + (size_t)(T_)*CHc*DDc;                      \
    _Pragma("unroll")                                                            \
    for (int it=0; it<16; it++){                                                 \
      int seg = tid + it*256; int row = seg>>4, c = seg&15;                      \
      uint32_t dst = sbase + (BOFF) + row*256 + ((c ^ (row&7))<<4);              \
      CP16(dst, wsrc + (size_t)row*DDc + c*8);                                   \
    }                                                                            \
  }while(0)

  float acc[4][8][4];
  #pragma unroll
  for (int a=0;a<4;a++)
    #pragma unroll
    for (int b=0;b<8;b++)
      #pragma unroll
      for (int q=0;q<4;q++) acc[a][b][q]=0.f;

  LOAD_TAP(0, OFF_A0, OFF_B0); CP_COMMIT();

  for (int t=0; t<9; t++){
    if (t>0) __syncthreads();          // all warps done with buffers being overwritten
    if (t<8){
      if ((t+1)&1) LOAD_TAP(t+1, OFF_A1, OFF_B1);
      else         LOAD_TAP(t+1, OFF_A0, OFF_B0);
      CP_COMMIT();
    } else {
      // prefetch w1 tile [128 d][256 co] into B1
      #pragma unroll
      for (int it=0; it<16; it++){
        int seg = tid + it*256; int row = seg>>5, c = seg&31;
        uint32_t dst = sbase + OFF_B1 + row*512 + ((c ^ (row&7))<<4);
        CP16(dst, w1T + (size_t)row*CHc + c*8);
      }
      CP_COMMIT();
    }
    CP_WAIT(1);                         // current tap's tiles resident
    __syncthreads();

    const uint32_t abuf = sbase + ((t&1)? OFF_A1 : OFF_A0);
    const uint32_t bbuf = sbase + ((t&1)? OFF_B1 : OFF_B0);
    uint32_t Abase[4], Bbase[4];
    #pragma unroll
    for (int mb=0;mb<4;mb++) Abase[mb] = abuf + (wm*64 + mb*16 + lr)*256;
    #pragma unroll
    for (int nb2=0;nb2<4;nb2++) Bbase[nb2] = bbuf + (wn*64 + nb2*16 + lr)*256;

    #pragma unroll
    for (int kb=0; kb<8; kb++){
      const uint32_t off = (uint32_t)(((2*kb + hi) ^ sw) << 4);
      uint32_t a[4][4], bf[4][4];
      #pragma unroll
      for (int mb=0;mb<4;mb++) ldsm4(Abase[mb]+off, a[mb][0],a[mb][1],a[mb][2],a[mb][3]);
      #pragma unroll
      for (int nb2=0;nb2<4;nb2++) ldsm4(Bbase[nb2]+off, bf[nb2][0],bf[nb2][1],bf[nb2][2],bf[nb2][3]);
      #pragma unroll
      for (int mb=0;mb<4;mb++){
        #pragma unroll
        for (int nb2=0;nb2<4;nb2++){
          mma16816(acc[mb][2*nb2  ], a[mb][0],a[mb][1],a[mb][2],a[mb][3], bf[nb2][0], bf[nb2][2]);
          mma16816(acc[mb][2*nb2+1], a[mb][0],a[mb][1],a[mb][2],a[mb][3], bf[nb2][1], bf[nb2][3]);
        }
      }
    }
  }
  __syncthreads();

  // ---- epilogue 1: bias + exact gelu -> bf16 G [128 m][256 k] at OFF_A0 (64KB) ----
  {
    const int rq = lane>>2;             // row-in-tile quarter
    #pragma unroll
    for (int mb=0;mb<4;mb++){
      const int r0 = wm*64 + mb*16 + rq;
      const int r1 = r0 + 8;
      #pragma unroll
      for (int nb=0;nb<8;nb++){
        const int col = wn*64 + nb*8 + 2*(lane&3);
        float2 bv = *(const float2*)(b3 + col);
        float v0 = acc[mb][nb][0] + bv.x;
        float v1 = acc[mb][nb][1] + bv.y;
        float v2 = acc[mb][nb][2] + bv.x;
        float v3 = acc[mb][nb][3] + bv.y;
        v0 = 0.5f*v0*(1.0f+erff(v0*0.7071067811865476f));
        v1 = 0.5f*v1*(1.0f+erff(v1*0.7071067811865476f));
        v2 = 0.5f*v2*(1.0f+erff(v2*0.7071067811865476f));
        v3 = 0.5f*v3*(1.0f+erff(v3*0.7071067811865476f));
        const int chunk = col>>3, wb = (col&7)*2;
        uint32_t o0 = (uint32_t)(r0*512 + ((chunk ^ (r0&7))<<4) + wb);
        uint32_t o1 = (uint32_t)(r1*512 + ((chunk ^ (r1&7))<<4) + wb);
        __nv_bfloat162 h0 = __floats2bfloat162_rn(v0, v1);
        __nv_bfloat162 h1 = __floats2bfloat162_rn(v2, v3);
        *(uint32_t*)(smem + OFF_A0 + o0) = *(uint32_t*)&h0;
        *(uint32_t*)(smem + OFF_A0 + o1) = *(uint32_t*)&h1;
      }
    }
  }
  CP_WAIT(0);                            // w1 tile resident
  __syncthreads();                       // G visible to all warps

  // ---- 1x1 GEMM: D2[128,128] = G[128,256] @ w1T^T ----
  float a2[4][4][4];
  #pragma unroll
  for (int a=0;a<4;a++)
    #pragma unroll
    for (int b=0;b<4;b++)
      #pragma unroll
      for (int q=0;q<4;q++) a2[a][b][q]=0.f;
  {
    uint32_t Gbase[4], Wbase[2];
    #pragma unroll
    for (int mb=0;mb<4;mb++) Gbase[mb] = sbase + OFF_A0 + (wm*64 + mb*16 + lr)*512;
    #pragma unroll
    for (int nb2=0;nb2<2;nb2++) Wbase[nb2] = sbase + OFF_B1 + (wn*32 + nb2*16 + lr)*512;

    #pragma unroll
    for (int kb=0; kb<16; kb++){
      const uint32_t off = (uint32_t)(((2*kb + hi) ^ sw) << 4);
      uint32_t a[4][4], bf[2][4];
      #pragma unroll
      for (int mb=0;mb<4;mb++) ldsm4(Gbase[mb]+off, a[mb][0],a[mb][1],a[mb][2],a[mb][3]);
      #pragma unroll
      for (int nb2=0;nb2<2;nb2++) ldsm4(Wbase[nb2]+off, bf[nb2][0],bf[nb2][1],bf[nb2][2],bf[nb2][3]);
      #pragma unroll
      for (int mb=0;mb<4;mb++){
        #pragma unroll
        for (int nb2=0;nb2<2;nb2++){
          mma16816(a2[mb][2*nb2  ], a[mb][0],a[mb][1],a[mb][2],a[mb][3], bf[nb2][0], bf[nb2][2]);
          mma16816(a2[mb][2*nb2+1], a[mb][0],a[mb][1],a[mb][2],a[mb][3], bf[nb2][1], bf[nb2][3]);
        }
      }
    }
  }

  // ---- epilogue 2: bias + residual RMW into g_Y ----
  {
    const int rq = lane>>2;
    #pragma unroll
    for (int mb=0;mb<4;mb++){
      const int r0 = wm*64 + mb*16 + rq;
      float* y0 = g_Y + ((size_t)blockIdx.x*128 + r0)*DDc;
      #pragma unroll
      for (int nb=0;nb<4;nb++){
        const int d = wn*32 + nb*8 + 2*(lane&3);
        float2 bv = *(const float2*)(b1 + d);
        float2 ya = *(float2*)(y0 + d);
        ya.x += a2[mb][nb][0] + bv.x;
        ya.y += a2[mb][nb][1] + bv.y;
        *(float2*)(y0 + d) = ya;
        float2 yb = *(float2*)(y0 + 8*DDc + d);
        yb.x += a2[mb][nb][2] + bv.x;
        yb.y += a2[mb][nb][3] + bv.y;
        *(float2*)(y0 + 8*DDc + d) = yb;
      }
    }
  }
  #undef LOAD_TAP
}

// ---------------- launch ----------------
extern "C" void kernel_launch(void* const* d_in, const int* in_sizes, int n_in,
                              void* d_out, int out_size){
  const float* X        = (const float*)d_in[0];
  const int*   coords   = (const int*)  d_in[1];
  const float* P        = (const float*)d_in[2];
  const float* ln_scale = (const float*)d_in[3];
  const float* ln_bias  = (const float*)d_in[4];
  const float* w3       = (const float*)d_in[5];
  const float* b3       = (const float*)d_in[6];
  const float* w1       = (const float*)d_in[7];
  const float* b1       = (const float*)d_in[8];
  float* out = (float*)d_out;

  const int SMEM_SZ = 197632 + 1024;     // tiles + control + align slack
  cudaFuncSetAttribute(k_conv, cudaFuncAttributeMaxDynamicSharedMemorySize, SMEM_SZ);

  k_inv <<<1, 1024>>>(coords);
  k_fill<<<86528, 256>>>(X, P);
  k_zero<<<12544, 256>>>();
  k_prep3<<<4608, 256>>>(w3);
  k_prep1<<<512, 256>>>(w1);

  for (int l=0; l<4; l++){
    k_ln  <<<21632, 256>>>(ln_scale + l*DDc, ln_bias + l*DDc);
    k_conv<<<NTILE, 256, SMEM_SZ>>>(l, b3 + l*CHc, b1 + l*DDc);
  }

  k_gather<<<79872, 256>>>(coords, out);
}